// round 1
// baseline (speedup 1.0000x reference)
#include <cuda_runtime.h>
#include <math.h>

#define S    4096
#define DM   1024
#define DI   2048
#define NST  16
#define RB   96     // DT_RANK + 2*D_STATE = 64 + 32

// ---------------- scratch (device globals; no runtime allocation) ----------
__device__ float g_enc[S * DM];
__device__ float g_h[S * DM];
__device__ float g_xz[S * 2 * DI];
__device__ float g_u[S * DI];
__device__ float g_dbc[S * RB];
__device__ float g_delta[S * DI];
__device__ float g_y[S * DI];
__device__ float g_gated[S * DI];

// ---------------- block reduction helper (256 threads) ---------------------
__device__ __forceinline__ float block_sum(float v, float* red) {
#pragma unroll
    for (int o = 16; o; o >>= 1) v += __shfl_xor_sync(0xffffffffu, v, o);
    if ((threadIdx.x & 31) == 0) red[threadIdx.x >> 5] = v;
    __syncthreads();
    float t = red[0] + red[1] + red[2] + red[3] + red[4] + red[5] + red[6] + red[7];
    __syncthreads();   // protect red[] for a subsequent call
    return t;
}

// ---------------- LayerNorm (optionally fused add), W in {1024, 2048} ------
__global__ void ln_kernel(const float* __restrict__ src,
                          const float* __restrict__ add,
                          const float* __restrict__ gam,
                          const float* __restrict__ bet,
                          float* __restrict__ out, int W, float eps) {
    __shared__ float red[8];
    const int r = blockIdx.x;
    const int nloc = W >> 8;           // per-thread elements (4 or 8)
    float vals[8];
    float s = 0.f;
    for (int j = 0; j < nloc; j++) {
        int i = threadIdx.x + (j << 8);
        float v = src[(size_t)r * W + i];
        if (add) v += add[(size_t)r * W + i];
        vals[j] = v;
        s += v;
    }
    float mean = block_sum(s, red) / (float)W;
    float s2 = 0.f;
    for (int j = 0; j < nloc; j++) {
        float d = vals[j] - mean;
        s2 += d * d;
    }
    float rstd = rsqrtf(block_sum(s2, red) / (float)W + eps);
    for (int j = 0; j < nloc; j++) {
        int i = threadIdx.x + (j << 8);
        out[(size_t)r * W + i] = (vals[j] - mean) * rstd * gam[i] + bet[i];
    }
}

// ---------------- LN(y) * silu(z) (W = 2048), z = xz[:, 2048:] -------------
__global__ void ln_gate_kernel(const float* __restrict__ y,
                               const float* __restrict__ xz,
                               const float* __restrict__ gam,
                               const float* __restrict__ bet,
                               float* __restrict__ out) {
    __shared__ float red[8];
    const int r = blockIdx.x;
    float vals[8];
    float s = 0.f;
#pragma unroll
    for (int j = 0; j < 8; j++) {
        int i = threadIdx.x + (j << 8);
        float v = y[(size_t)r * DI + i];
        vals[j] = v;
        s += v;
    }
    float mean = block_sum(s, red) / (float)DI;
    float s2 = 0.f;
#pragma unroll
    for (int j = 0; j < 8; j++) {
        float d = vals[j] - mean;
        s2 += d * d;
    }
    float rstd = rsqrtf(block_sum(s2, red) / (float)DI + 1e-5f);
#pragma unroll
    for (int j = 0; j < 8; j++) {
        int i = threadIdx.x + (j << 8);
        float z = xz[(size_t)r * (2 * DI) + DI + i];
        float sz = z / (1.f + expf(-z));
        out[(size_t)r * DI + i] = ((vals[j] - mean) * rstd * gam[i] + bet[i]) * sz;
    }
}

// ---------------- depthwise conv1d k=3 pad=1 over x1 = xz[:, :2048] --------
__global__ void conv_kernel(const float* __restrict__ xz,
                            const float* __restrict__ w,
                            const float* __restrict__ b,
                            float* __restrict__ u) {
    int idx = blockIdx.x * blockDim.x + threadIdx.x;   // S*DI threads
    int c = idx & (DI - 1);
    int s = idx >> 11;
    float w0 = w[c * 3 + 0], w1 = w[c * 3 + 1], w2 = w[c * 3 + 2];
    float acc = b[c] + w1 * xz[(size_t)s * (2 * DI) + c];
    if (s > 0)     acc += w0 * xz[(size_t)(s - 1) * (2 * DI) + c];
    if (s < S - 1) acc += w2 * xz[(size_t)(s + 1) * (2 * DI) + c];
    u[(size_t)s * DI + c] = acc;
}

// ---------------- GEMM NT: C[M,N] = A[M,K] * B[N,K]^T (+bias,+skip,act) ----
// 128x128x8 tile, 256 threads, 8x8 microtile. M multiple of 128, K mult of 8.
__global__ __launch_bounds__(256)
void gemm_nt(const float* __restrict__ A, int lda,
             const float* __restrict__ B, int K,    // ldb == K
             const float* __restrict__ bias,
             const float* __restrict__ skip,
             float* __restrict__ C, int ldc,
             int N, int act) {
    __shared__ __align__(16) float As[8][128];
    __shared__ __align__(16) float Bs[8][128];
    const int tid = threadIdx.x;
    const int bm = blockIdx.y * 128;
    const int bn = blockIdx.x * 128;
    const int lr = tid >> 1;
    const int lk = (tid & 1) << 2;
    const int tx = tid & 15;
    const int ty = tid >> 4;

    const float* Ap = A + (size_t)(bm + lr) * lda + lk;
    const int brow = bn + lr;
    const float* Bp = B + (size_t)brow * K + lk;
    const bool bvalid = (brow < N);

    float acc[8][8];
#pragma unroll
    for (int i = 0; i < 8; i++)
#pragma unroll
        for (int j = 0; j < 8; j++) acc[i][j] = 0.f;

    for (int k0 = 0; k0 < K; k0 += 8) {
        float4 av = *(const float4*)(Ap + k0);
        float4 bv = bvalid ? *(const float4*)(Bp + k0) : make_float4(0.f, 0.f, 0.f, 0.f);
        __syncthreads();
        As[lk + 0][lr] = av.x; As[lk + 1][lr] = av.y;
        As[lk + 2][lr] = av.z; As[lk + 3][lr] = av.w;
        Bs[lk + 0][lr] = bv.x; Bs[lk + 1][lr] = bv.y;
        Bs[lk + 2][lr] = bv.z; Bs[lk + 3][lr] = bv.w;
        __syncthreads();
#pragma unroll
        for (int kk = 0; kk < 8; kk++) {
            float4 a0 = *(const float4*)&As[kk][ty * 4];
            float4 a1 = *(const float4*)&As[kk][64 + ty * 4];
            float4 b0 = *(const float4*)&Bs[kk][tx * 4];
            float4 b1 = *(const float4*)&Bs[kk][64 + tx * 4];
            float ar[8] = {a0.x, a0.y, a0.z, a0.w, a1.x, a1.y, a1.z, a1.w};
            float br[8] = {b0.x, b0.y, b0.z, b0.w, b1.x, b1.y, b1.z, b1.w};
#pragma unroll
            for (int i = 0; i < 8; i++)
#pragma unroll
                for (int j = 0; j < 8; j++)
                    acc[i][j] = fmaf(ar[i], br[j], acc[i][j]);
        }
    }

#pragma unroll
    for (int i = 0; i < 8; i++) {
        int m = bm + ((i < 4) ? (ty * 4 + i) : (64 + ty * 4 + i - 4));
#pragma unroll
        for (int j = 0; j < 8; j++) {
            int n = bn + ((j < 4) ? (tx * 4 + j) : (64 + tx * 4 + j - 4));
            if (n < N) {
                float v = acc[i][j];
                if (bias) v += bias[n];
                if (skip) v += skip[(size_t)m * ldc + n];
                if (act == 1) v = (v > 20.f) ? v : log1pf(expf(v));
                C[(size_t)m * ldc + n] = v;
            }
        }
    }
}

// ---------------- selective scan: 16 lanes per d-channel -------------------
// h[d,n](t) = exp(dt[t,d]*A[d,n]) * h + dt*u*B[t,n];  y[t,d] = sum_n h*C[t,n] + D[d]*u
__global__ void scan_kernel(const float* __restrict__ u,
                            const float* __restrict__ delta,
                            const float* __restrict__ dbc,
                            const float* __restrict__ A_log,
                            const float* __restrict__ Dp,
                            float* __restrict__ y) {
    const int tid = threadIdx.x;       // 256 threads: 16 d-channels x 16 states
    const int nlane = tid & 15;
    const int dloc = tid >> 4;
    const int d = blockIdx.x * 16 + dloc;
    const float A = -__expf(A_log[d * NST + nlane]);
    const float Dv = Dp[d];
    float h = 0.f;
    for (int t = 0; t < S; t++) {
        float dt = delta[(size_t)t * DI + d];
        float uu = u[(size_t)t * DI + d];
        float Bn = dbc[(size_t)t * RB + 64 + nlane];
        float Cn = dbc[(size_t)t * RB + 80 + nlane];
        float dA = __expf(dt * A);
        h = dA * h + (dt * uu) * Bn;
        float p = h * Cn;
        p += __shfl_xor_sync(0xffffffffu, p, 1);
        p += __shfl_xor_sync(0xffffffffu, p, 2);
        p += __shfl_xor_sync(0xffffffffu, p, 4);
        p += __shfl_xor_sync(0xffffffffu, p, 8);
        if (nlane == 0) y[(size_t)t * DI + d] = p + Dv * uu;
    }
}

// ---------------- launcher --------------------------------------------------
extern "C" void kernel_launch(void* const* d_in, const int* in_sizes, int n_in,
                              void* d_out, int out_size) {
    const float* x         = (const float*)d_in[0];
    const float* pos_enc   = (const float*)d_in[1];
    const float* ln_g      = (const float*)d_in[2];
    const float* ln_b      = (const float*)d_in[3];
    const float* innorm_g  = (const float*)d_in[4];
    const float* innorm_b  = (const float*)d_in[5];
    const float* in_proj_w = (const float*)d_in[6];
    const float* in_proj_b = (const float*)d_in[7];
    const float* conv_w    = (const float*)d_in[8];
    const float* conv_b    = (const float*)d_in[9];
    const float* deltaBC_w = (const float*)d_in[10];
    const float* dt_proj_w = (const float*)d_in[11];
    const float* dt_proj_b = (const float*)d_in[12];
    const float* A_log     = (const float*)d_in[13];
    const float* Dp        = (const float*)d_in[14];
    const float* outnorm_g = (const float*)d_in[15];
    const float* outnorm_b = (const float*)d_in[16];
    const float* out_proj_w= (const float*)d_in[17];
    const float* out_proj_b= (const float*)d_in[18];

    float *enc, *h, *xz, *u, *dbc, *delta, *y, *gated;
    cudaGetSymbolAddress((void**)&enc,   g_enc);
    cudaGetSymbolAddress((void**)&h,     g_h);
    cudaGetSymbolAddress((void**)&xz,    g_xz);
    cudaGetSymbolAddress((void**)&u,     g_u);
    cudaGetSymbolAddress((void**)&dbc,   g_dbc);
    cudaGetSymbolAddress((void**)&delta, g_delta);
    cudaGetSymbolAddress((void**)&y,     g_y);
    cudaGetSymbolAddress((void**)&gated, g_gated);

    // enc = LN(x + pos_enc), eps=1e-6
    ln_kernel<<<S, 256>>>(x, pos_enc, ln_g, ln_b, enc, DM, 1e-6f);

    for (int i = 0; i < 4; i++) {
        // h = LN(enc), eps=1e-5
        ln_kernel<<<S, 256>>>(enc, nullptr, innorm_g + i * DM, innorm_b + i * DM,
                              h, DM, 1e-5f);
        // xz = h @ in_proj_w^T + b   [4096, 4096]
        gemm_nt<<<dim3(32, 32), 256>>>(h, DM,
                                       in_proj_w + (size_t)i * 2 * DI * DM, DM,
                                       in_proj_b + (size_t)i * 2 * DI,
                                       nullptr, xz, 2 * DI, 2 * DI, 0);
        // u = depthwise conv(x1) + b
        conv_kernel<<<(S * DI) / 256, 256>>>(xz, conv_w + (size_t)i * DI * 3,
                                             conv_b + (size_t)i * DI, u);
        // dbc = u @ deltaBC_w^T      [4096, 96]
        gemm_nt<<<dim3(1, 32), 256>>>(u, DI,
                                      deltaBC_w + (size_t)i * RB * DI, DI,
                                      nullptr, nullptr, dbc, RB, RB, 0);
        // delta = softplus(dbc[:, :64] @ dt_proj_w^T + b)   [4096, 2048]
        gemm_nt<<<dim3(16, 32), 256>>>(dbc, RB,
                                       dt_proj_w + (size_t)i * DI * 64, 64,
                                       dt_proj_b + (size_t)i * DI,
                                       nullptr, delta, DI, DI, 1);
        // selective scan -> y (incl. + u*D)
        scan_kernel<<<DI / 16, 256>>>(u, delta, dbc,
                                      A_log + (size_t)i * DI * NST,
                                      Dp + (size_t)i * DI, y);
        // gated = LN(y) * silu(z1)
        ln_gate_kernel<<<S, 256>>>(y, xz, outnorm_g + (size_t)i * DI,
                                   outnorm_b + (size_t)i * DI, gated);
        // enc = gated @ out_proj_w^T + b + enc(skip)
        float* dest = (i == 3) ? (float*)d_out : enc;
        gemm_nt<<<dim3(8, 32), 256>>>(gated, DI,
                                      out_proj_w + (size_t)i * DM * DI, DI,
                                      out_proj_b + (size_t)i * DM,
                                      enc, dest, DM, DM, 0);
    }
}